// round 5
// baseline (speedup 1.0000x reference)
#include <cuda_runtime.h>
#include <cstdint>

// Problem constants
#define Bc   8
#define Tc   256
#define Uc   64
#define Dc   640
#define Vc   1024
#define K2c  1280
#define MOUT (Bc*Tc*Uc)     // 131072 output rows

// P = ReLU(pred) @ Wp^T + bias, precomputed once (2 MB scratch)
__device__ __align__(16) float g_P[Bc * Uc * Vc];

__device__ __forceinline__ uint32_t f2tf(float x) {
    uint32_t r;
    asm("cvt.rna.tf32.f32 %0, %1;" : "=r"(r) : "f"(x));
    return r;
}

// ---------------------------------------------------------------------------
// P kernel: 64x128 tiles, grid (V/128=8, MP/64=8), 256 threads.
// Also writes the passthrough length tail from block (0,0).
// ---------------------------------------------------------------------------
__global__ __launch_bounds__(256) void p_gemm(
    const float* __restrict__ pred,
    const float* __restrict__ W,
    const float* __restrict__ bias,
    float* __restrict__ out,
    const int* __restrict__ slen,
    const int* __restrict__ tlen,
    int writeTail)
{
    __shared__ uint32_t As[64][36];
    __shared__ uint32_t Bs[128][36];

    const int tid  = threadIdx.x;
    const int warp = tid >> 5;
    const int lane = tid & 31;
    const int g    = lane >> 2;
    const int q    = lane & 3;
    const int bn0  = blockIdx.x * 128;
    const int bm0  = blockIdx.y * 64;     // row in [0, 512)
    const int lr   = tid >> 3;
    const int lc   = (tid & 7) * 4;
    const int mg   = warp & 3;            // 4 m-groups x 16 rows
    const int ng   = warp >> 2;           // 2 n-groups x 64 cols

    float c[8][4];
#pragma unroll
    for (int nt = 0; nt < 8; nt++)
#pragma unroll
        for (int r = 0; r < 4; r++) c[nt][r] = 0.f;

    float4 ra[2], rw[4];
#pragma unroll
    for (int i = 0; i < 2; i++)
        ra[i] = *(const float4*)&pred[(size_t)(bm0 + lr + i * 32) * Dc + lc];
#pragma unroll
    for (int i = 0; i < 4; i++)
        rw[i] = *(const float4*)&W[(size_t)(bn0 + lr + i * 32) * K2c + Dc + lc];

    for (int k0 = 0; k0 < Dc; k0 += 32) {
#pragma unroll
        for (int i = 0; i < 2; i++) {
            int row = lr + i * 32;
            As[row][lc+0] = f2tf(fmaxf(ra[i].x, 0.f));
            As[row][lc+1] = f2tf(fmaxf(ra[i].y, 0.f));
            As[row][lc+2] = f2tf(fmaxf(ra[i].z, 0.f));
            As[row][lc+3] = f2tf(fmaxf(ra[i].w, 0.f));
        }
#pragma unroll
        for (int i = 0; i < 4; i++) {
            int row = lr + i * 32;
            Bs[row][lc+0] = f2tf(rw[i].x);
            Bs[row][lc+1] = f2tf(rw[i].y);
            Bs[row][lc+2] = f2tf(rw[i].z);
            Bs[row][lc+3] = f2tf(rw[i].w);
        }
        __syncthreads();
        if (k0 + 32 < Dc) {
#pragma unroll
            for (int i = 0; i < 2; i++)
                ra[i] = *(const float4*)&pred[(size_t)(bm0 + lr + i * 32) * Dc + k0 + 32 + lc];
#pragma unroll
            for (int i = 0; i < 4; i++)
                rw[i] = *(const float4*)&W[(size_t)(bn0 + lr + i * 32) * K2c + Dc + k0 + 32 + lc];
        }
#pragma unroll
        for (int kk = 0; kk < 4; kk++) {
            uint32_t af[4];
            af[0] = As[mg*16 + g    ][kk*8 + q    ];
            af[1] = As[mg*16 + g + 8][kk*8 + q    ];
            af[2] = As[mg*16 + g    ][kk*8 + q + 4];
            af[3] = As[mg*16 + g + 8][kk*8 + q + 4];
#pragma unroll
            for (int nt = 0; nt < 8; nt++) {
                int n = ng*64 + nt*8 + g;
                uint32_t b0 = Bs[n][kk*8 + q];
                uint32_t b1 = Bs[n][kk*8 + q + 4];
                asm volatile(
                    "mma.sync.aligned.m16n8k8.row.col.f32.tf32.tf32.f32 "
                    "{%0,%1,%2,%3}, {%4,%5,%6,%7}, {%8,%9}, {%0,%1,%2,%3};\n"
                    : "+f"(c[nt][0]), "+f"(c[nt][1]), "+f"(c[nt][2]), "+f"(c[nt][3])
                    : "r"(af[0]), "r"(af[1]), "r"(af[2]), "r"(af[3]),
                      "r"(b0), "r"(b1));
            }
        }
        __syncthreads();
    }

    {
        int row = bm0 + mg * 16 + g;
#pragma unroll
        for (int nt = 0; nt < 8; nt++) {
            int col = bn0 + ng*64 + nt*8 + q*2;
            float b0 = bias[col], b1 = bias[col + 1];
            g_P[(size_t)row * Vc + col]           = c[nt][0] + b0;
            g_P[(size_t)row * Vc + col + 1]       = c[nt][1] + b1;
            g_P[(size_t)(row + 8) * Vc + col]     = c[nt][2] + b0;
            g_P[(size_t)(row + 8) * Vc + col + 1] = c[nt][3] + b1;
        }
    }

    if (writeTail && blockIdx.x == 0 && blockIdx.y == 0 && tid < 16) {
        size_t tb = (size_t)MOUT * Vc;
        if (tid < 8) out[tb + tid] = (float)slen[tid];
        else         out[tb + tid] = (float)tlen[tid - 8];
    }
}

// 54.5 KB dynamic smem: 4 blocks/SM -> 218 KB
struct __align__(16) Smem {
    float P[64][128];                                   // 32 KB, persistent
    union {
        struct { uint32_t As[32][36]; uint32_t Bs[128][36]; } g;  // 22.5 KB
        float E[32][128];                               // 16 KB
    } u;
};

// ---------------------------------------------------------------------------
// Fused E-gemm + expand. grid = (V/128=8, 8*B=64), 256 threads, 4 blocks/SM.
//   Block (bx, by): b = by>>3, t0 = (by&7)*32, v-cols [bx*128, +128)
// Phase 0: stage P tile (64x128) from g_P into smem
// Phase E: cE[32 t x 128 v] = ReLU(enc) @ We^T   (16 accumulator regs)
// Phase C: out[b,t,u,v] = E[t][v] + P[u][v]      (1 MB per block)
// ---------------------------------------------------------------------------
__global__ __launch_bounds__(256, 4) void fused_joiner(
    const float* __restrict__ enc,
    const float* __restrict__ W,
    float4* __restrict__ out)
{
    extern __shared__ char smem_raw[];
    Smem& sm = *reinterpret_cast<Smem*>(smem_raw);

    const int tid  = threadIdx.x;
    const int warp = tid >> 5;
    const int lane = tid & 31;
    const int g    = lane >> 2;
    const int q    = lane & 3;
    const int bn0  = blockIdx.x * 128;
    const int b    = blockIdx.y >> 3;
    const int bt0  = b * Tc + (blockIdx.y & 7) * 32;

    const int lr = tid >> 3;        // 0..31
    const int lc = (tid & 7) * 4;   // 0,4..28
    const int mg = warp & 1;        // 2 m-groups x 16 rows (32 total)
    const int ng = warp >> 1;       // 4 n-groups x 32 cols (128 total)

    // ---- Phase 0: stage P tile into smem (32 KB from L2) ----
    {
        const float4* P4 = (const float4*)g_P;
#pragma unroll
        for (int i = 0; i < 8; i++) {
            int idx = tid + i * 256;            // 2048 float4
            int r = idx >> 5, cq = idx & 31;
            ((float4*)sm.P[r])[cq] = P4[(size_t)(b * Uc + r) * 256 + blockIdx.x * 32 + cq];
        }
    }

    // ---- Phase E: 32 x 128 gemm ----
    float c[4][4];
#pragma unroll
    for (int nt = 0; nt < 4; nt++)
#pragma unroll
        for (int r = 0; r < 4; r++) c[nt][r] = 0.f;

    float4 ra, rw[4];
    ra = *(const float4*)&enc[(size_t)(bt0 + lr) * Dc + lc];
#pragma unroll
    for (int i = 0; i < 4; i++)
        rw[i] = *(const float4*)&W[(size_t)(bn0 + lr + i * 32) * K2c + lc];

    for (int k0 = 0; k0 < Dc; k0 += 32) {
        sm.u.g.As[lr][lc+0] = f2tf(fmaxf(ra.x, 0.f));
        sm.u.g.As[lr][lc+1] = f2tf(fmaxf(ra.y, 0.f));
        sm.u.g.As[lr][lc+2] = f2tf(fmaxf(ra.z, 0.f));
        sm.u.g.As[lr][lc+3] = f2tf(fmaxf(ra.w, 0.f));
#pragma unroll
        for (int i = 0; i < 4; i++) {
            int row = lr + i * 32;
            sm.u.g.Bs[row][lc+0] = f2tf(rw[i].x);
            sm.u.g.Bs[row][lc+1] = f2tf(rw[i].y);
            sm.u.g.Bs[row][lc+2] = f2tf(rw[i].z);
            sm.u.g.Bs[row][lc+3] = f2tf(rw[i].w);
        }
        __syncthreads();
        if (k0 + 32 < Dc) {
            ra = *(const float4*)&enc[(size_t)(bt0 + lr) * Dc + k0 + 32 + lc];
#pragma unroll
            for (int i = 0; i < 4; i++)
                rw[i] = *(const float4*)&W[(size_t)(bn0 + lr + i * 32) * K2c + k0 + 32 + lc];
        }
#pragma unroll
        for (int kk = 0; kk < 4; kk++) {
            uint32_t af[4];
            af[0] = sm.u.g.As[mg*16 + g    ][kk*8 + q    ];
            af[1] = sm.u.g.As[mg*16 + g + 8][kk*8 + q    ];
            af[2] = sm.u.g.As[mg*16 + g    ][kk*8 + q + 4];
            af[3] = sm.u.g.As[mg*16 + g + 8][kk*8 + q + 4];
#pragma unroll
            for (int nt = 0; nt < 4; nt++) {
                int n = ng*32 + nt*8 + g;
                uint32_t b0 = sm.u.g.Bs[n][kk*8 + q];
                uint32_t b1 = sm.u.g.Bs[n][kk*8 + q + 4];
                asm volatile(
                    "mma.sync.aligned.m16n8k8.row.col.f32.tf32.tf32.f32 "
                    "{%0,%1,%2,%3}, {%4,%5,%6,%7}, {%8,%9}, {%0,%1,%2,%3};\n"
                    : "+f"(c[nt][0]), "+f"(c[nt][1]), "+f"(c[nt][2]), "+f"(c[nt][3])
                    : "r"(af[0]), "r"(af[1]), "r"(af[2]), "r"(af[3]),
                      "r"(b0), "r"(b1));
            }
        }
        __syncthreads();
    }

    // ---- write E tile to smem ----
    {
        int r0 = mg * 16 + g;
#pragma unroll
        for (int nt = 0; nt < 4; nt++) {
            int col = ng*32 + nt*8 + q*2;
            sm.u.E[r0    ][col    ] = c[nt][0];
            sm.u.E[r0    ][col + 1] = c[nt][1];
            sm.u.E[r0 + 8][col    ] = c[nt][2];
            sm.u.E[r0 + 8][col + 1] = c[nt][3];
        }
    }
    __syncthreads();

    // ---- Phase C: expand. warp owns 4 t-rows; loop u: 1 LDS + 4 STG ----
    const int vq = lane;
    float4 e[4];
    size_t obase[4];
#pragma unroll
    for (int ti = 0; ti < 4; ti++) {
        int tl = warp * 4 + ti;
        e[ti] = ((const float4*)sm.u.E[tl])[vq];
        obase[ti] = (size_t)(bt0 + tl) * Uc * 256 + blockIdx.x * 32 + vq;
    }
#pragma unroll 4
    for (int u = 0; u < Uc; u++) {
        float4 p = ((const float4*)sm.P[u])[vq];
#pragma unroll
        for (int ti = 0; ti < 4; ti++) {
            float4 r;
            r.x = e[ti].x + p.x; r.y = e[ti].y + p.y;
            r.z = e[ti].z + p.z; r.w = e[ti].w + p.w;
            out[obase[ti] + (size_t)u * 256] = r;
        }
    }
}

extern "C" void kernel_launch(void* const* d_in, const int* in_sizes, int n_in,
                              void* d_out, int out_size)
{
    const float* enc  = (const float*)d_in[0];  // [B,T,D]
    const int*   slen = (const int*)  d_in[1];  // [B]
    const float* pred = (const float*)d_in[2];  // [B,U,D]
    const int*   tlen = (const int*)  d_in[3];  // [B]
    const float* W    = (const float*)d_in[4];  // [V, 2D]
    const float* bias = (const float*)d_in[5];  // [V]
    float* out = (float*)d_out;

    int writeTail = (out_size >= (int)((size_t)MOUT * Vc + 16)) ? 1 : 0;

    // P = ReLU(pred) @ Wp^T + bias  (+ length tail)
    p_gemm<<<dim3(Vc / 128, (Bc * Uc) / 64), 256>>>(
        pred, W, bias, out, slen, tlen, writeTail);

    int smemBytes = (int)sizeof(Smem);
    cudaFuncSetAttribute(fused_joiner,
                         cudaFuncAttributeMaxDynamicSharedMemorySize, smemBytes);
    fused_joiner<<<dim3(Vc / 128, 8 * Bc), 256, smemBytes>>>(
        enc, W, (float4*)out);
}

// round 6
// speedup vs baseline: 1.2663x; 1.2663x over previous
#include <cuda_runtime.h>
#include <cstdint>

// Problem constants
#define Bc   8
#define Tc   256
#define Uc   64
#define Dc   640
#define Vc   1024
#define K2c  1280
#define MOUT (Bc*Tc*Uc)     // 131072 output rows

__device__ __forceinline__ uint32_t f2tf(float x) {
    uint32_t r;
    asm("cvt.rna.tf32.f32 %0, %1;" : "=r"(r) : "f"(x));
    return r;
}

// 68 KB dynamic shared memory, 1 block/SM
struct __align__(16) Smem {
    float P[64][128];                                   // 32 KB, persistent
    union {
        struct { uint32_t As[128][36]; uint32_t Bs[128][36]; } g;  // 36 KB staging
        float E[32][128];                               // 16 KB store slab
    } u;
};

// ---------------------------------------------------------------------------
// ONE kernel. grid = (V/128 = 8, 2*B = 16), 512 threads (16 warps).
//   Block (bx, by): b = by>>1, t0 = (by&1)*128, v-cols [bx*128, +128)
// Phase P: cP[64 u x 128 v] = ReLU(pred) @ Wp^T + bias -> smem P
// Phase E: cE[128 t x 128 v] = ReLU(enc) @ We^T  (32 acc regs/thread)
// Phase C: 4 slabs of 32 t: out[b,t,u,v] = E + P via evict-first stores
// ---------------------------------------------------------------------------
__global__ __launch_bounds__(512, 1) void fused_joiner(
    const float* __restrict__ enc,
    const float* __restrict__ pred,
    const float* __restrict__ W,
    const float* __restrict__ bias,
    float4* __restrict__ out,
    const int* __restrict__ slen,
    const int* __restrict__ tlen,
    int writeTail)
{
    extern __shared__ char smem_raw[];
    Smem& sm = *reinterpret_cast<Smem*>(smem_raw);

    const int tid  = threadIdx.x;
    const int warp = tid >> 5;       // 0..15
    const int lane = tid & 31;
    const int g    = lane >> 2;      // 0..7
    const int q    = lane & 3;       // 0..3
    const int bn0  = blockIdx.x * 128;
    const int b    = blockIdx.y >> 1;
    const int bt0  = b * Tc + (blockIdx.y & 1) * 128;

    const int lr = tid >> 3;         // 0..63 (staging row)
    const int lc = (tid & 7) * 4;    // 0,4..28 (staging k-col)

    float4 ra[2], rw[2];

    // ===================== Phase P: 64 x 128 =====================
    // warp layout: mgP = warp&3 (16 rows each), ngP = warp>>2 (32 cols each)
    const int mgP = warp & 3;
    const int ngP = warp >> 2;
    float cP[4][4];
#pragma unroll
    for (int nt = 0; nt < 4; nt++)
#pragma unroll
        for (int r = 0; r < 4; r++) cP[nt][r] = 0.f;

    ra[0] = *(const float4*)&pred[(size_t)(b * Uc + lr) * Dc + lc];
#pragma unroll
    for (int i = 0; i < 2; i++)
        rw[i] = *(const float4*)&W[(size_t)(bn0 + lr + i * 64) * K2c + Dc + lc];

    for (int k0 = 0; k0 < Dc; k0 += 32) {
        sm.u.g.As[lr][lc+0] = f2tf(fmaxf(ra[0].x, 0.f));
        sm.u.g.As[lr][lc+1] = f2tf(fmaxf(ra[0].y, 0.f));
        sm.u.g.As[lr][lc+2] = f2tf(fmaxf(ra[0].z, 0.f));
        sm.u.g.As[lr][lc+3] = f2tf(fmaxf(ra[0].w, 0.f));
#pragma unroll
        for (int i = 0; i < 2; i++) {
            int row = lr + i * 64;
            sm.u.g.Bs[row][lc+0] = f2tf(rw[i].x);
            sm.u.g.Bs[row][lc+1] = f2tf(rw[i].y);
            sm.u.g.Bs[row][lc+2] = f2tf(rw[i].z);
            sm.u.g.Bs[row][lc+3] = f2tf(rw[i].w);
        }
        __syncthreads();
        if (k0 + 32 < Dc) {
            ra[0] = *(const float4*)&pred[(size_t)(b * Uc + lr) * Dc + k0 + 32 + lc];
#pragma unroll
            for (int i = 0; i < 2; i++)
                rw[i] = *(const float4*)&W[(size_t)(bn0 + lr + i * 64) * K2c + Dc + k0 + 32 + lc];
        }
#pragma unroll
        for (int kk = 0; kk < 4; kk++) {
            uint32_t af[4];
            af[0] = sm.u.g.As[mgP*16 + g    ][kk*8 + q    ];
            af[1] = sm.u.g.As[mgP*16 + g + 8][kk*8 + q    ];
            af[2] = sm.u.g.As[mgP*16 + g    ][kk*8 + q + 4];
            af[3] = sm.u.g.As[mgP*16 + g + 8][kk*8 + q + 4];
#pragma unroll
            for (int nt = 0; nt < 4; nt++) {
                int n = ngP*32 + nt*8 + g;
                uint32_t b0 = sm.u.g.Bs[n][kk*8 + q];
                uint32_t b1 = sm.u.g.Bs[n][kk*8 + q + 4];
                asm volatile(
                    "mma.sync.aligned.m16n8k8.row.col.f32.tf32.tf32.f32 "
                    "{%0,%1,%2,%3}, {%4,%5,%6,%7}, {%8,%9}, {%0,%1,%2,%3};\n"
                    : "+f"(cP[nt][0]), "+f"(cP[nt][1]), "+f"(cP[nt][2]), "+f"(cP[nt][3])
                    : "r"(af[0]), "r"(af[1]), "r"(af[2]), "r"(af[3]),
                      "r"(b0), "r"(b1));
            }
        }
        __syncthreads();
    }

    // prefetch E phase k0=0 while dumping P
    ra[0] = *(const float4*)&enc[(size_t)(bt0 + lr) * Dc + lc];
    ra[1] = *(const float4*)&enc[(size_t)(bt0 + lr + 64) * Dc + lc];
#pragma unroll
    for (int i = 0; i < 2; i++)
        rw[i] = *(const float4*)&W[(size_t)(bn0 + lr + i * 64) * K2c + lc];

    // dump P (+bias) to persistent smem
    {
        int r0 = mgP * 16 + g;
#pragma unroll
        for (int nt = 0; nt < 4; nt++) {
            int col = ngP*32 + nt*8 + q*2;
            float b0 = bias[bn0 + col];
            float b1 = bias[bn0 + col + 1];
            sm.P[r0    ][col    ] = cP[nt][0] + b0;
            sm.P[r0    ][col + 1] = cP[nt][1] + b1;
            sm.P[r0 + 8][col    ] = cP[nt][2] + b0;
            sm.P[r0 + 8][col + 1] = cP[nt][3] + b1;
        }
    }

    // ===================== Phase E: 128 x 128 =====================
    // warp layout: mgE = warp&3 -> m-tiles {mgE, mgE+4} (16 rows each)
    //              ngE = warp>>2 (32 cols each)
    const int mgE = warp & 3;
    const int ngE = warp >> 2;
    float cE[2][4][4];
#pragma unroll
    for (int mt = 0; mt < 2; mt++)
#pragma unroll
        for (int nt = 0; nt < 4; nt++)
#pragma unroll
            for (int r = 0; r < 4; r++) cE[mt][nt][r] = 0.f;

    for (int k0 = 0; k0 < Dc; k0 += 32) {
#pragma unroll
        for (int i = 0; i < 2; i++) {
            int row = lr + i * 64;
            sm.u.g.As[row][lc+0] = f2tf(fmaxf(ra[i].x, 0.f));
            sm.u.g.As[row][lc+1] = f2tf(fmaxf(ra[i].y, 0.f));
            sm.u.g.As[row][lc+2] = f2tf(fmaxf(ra[i].z, 0.f));
            sm.u.g.As[row][lc+3] = f2tf(fmaxf(ra[i].w, 0.f));
            sm.u.g.Bs[row][lc+0] = f2tf(rw[i].x);
            sm.u.g.Bs[row][lc+1] = f2tf(rw[i].y);
            sm.u.g.Bs[row][lc+2] = f2tf(rw[i].z);
            sm.u.g.Bs[row][lc+3] = f2tf(rw[i].w);
        }
        __syncthreads();
        if (k0 + 32 < Dc) {
            ra[0] = *(const float4*)&enc[(size_t)(bt0 + lr) * Dc + k0 + 32 + lc];
            ra[1] = *(const float4*)&enc[(size_t)(bt0 + lr + 64) * Dc + k0 + 32 + lc];
#pragma unroll
            for (int i = 0; i < 2; i++)
                rw[i] = *(const float4*)&W[(size_t)(bn0 + lr + i * 64) * K2c + k0 + 32 + lc];
        }
#pragma unroll
        for (int kk = 0; kk < 4; kk++) {
            uint32_t af[2][4];
#pragma unroll
            for (int mt = 0; mt < 2; mt++) {
                int r0 = (mgE + 4*mt) * 16;
                af[mt][0] = sm.u.g.As[r0 + g    ][kk*8 + q    ];
                af[mt][1] = sm.u.g.As[r0 + g + 8][kk*8 + q    ];
                af[mt][2] = sm.u.g.As[r0 + g    ][kk*8 + q + 4];
                af[mt][3] = sm.u.g.As[r0 + g + 8][kk*8 + q + 4];
            }
#pragma unroll
            for (int nt = 0; nt < 4; nt++) {
                int n = ngE*32 + nt*8 + g;
                uint32_t b0 = sm.u.g.Bs[n][kk*8 + q];
                uint32_t b1 = sm.u.g.Bs[n][kk*8 + q + 4];
#pragma unroll
                for (int mt = 0; mt < 2; mt++) {
                    asm volatile(
                        "mma.sync.aligned.m16n8k8.row.col.f32.tf32.tf32.f32 "
                        "{%0,%1,%2,%3}, {%4,%5,%6,%7}, {%8,%9}, {%0,%1,%2,%3};\n"
                        : "+f"(cE[mt][nt][0]), "+f"(cE[mt][nt][1]),
                          "+f"(cE[mt][nt][2]), "+f"(cE[mt][nt][3])
                        : "r"(af[mt][0]), "r"(af[mt][1]), "r"(af[mt][2]), "r"(af[mt][3]),
                          "r"(b0), "r"(b1));
                }
            }
        }
        __syncthreads();
    }

    // ===================== Phase C: expand (4 slabs of 32 t) ===============
    const int vq = lane;
#pragma unroll 1
    for (int s = 0; s < 4; s++) {
        // warps owning m-tiles {2s, 2s+1} dump them into sm.u.E
#pragma unroll
        for (int mt = 0; mt < 2; mt++) {
            int mtile = mgE + 4 * mt;
            if ((mtile >> 1) == s) {
                int r0 = (mtile & 1) * 16 + g;
#pragma unroll
                for (int nt = 0; nt < 4; nt++) {
                    int col = ngE*32 + nt*8 + q*2;
                    sm.u.E[r0    ][col    ] = cE[mt][nt][0];
                    sm.u.E[r0    ][col + 1] = cE[mt][nt][1];
                    sm.u.E[r0 + 8][col    ] = cE[mt][nt][2];
                    sm.u.E[r0 + 8][col + 1] = cE[mt][nt][3];
                }
            }
        }
        __syncthreads();

        // warp w stores rows {2w, 2w+1} of the slab; loop u: 1 LDS + 2 STG.cs
        float4 e0 = ((const float4*)sm.u.E[warp * 2    ])[vq];
        float4 e1 = ((const float4*)sm.u.E[warp * 2 + 1])[vq];
        size_t ob0 = (size_t)(bt0 + s * 32 + warp * 2    ) * (Uc * 256)
                     + blockIdx.x * 32 + vq;
        size_t ob1 = ob0 + (size_t)(Uc * 256);
#pragma unroll 4
        for (int u = 0; u < Uc; u++) {
            float4 p = ((const float4*)sm.P[u])[vq];
            float4 r0, r1;
            r0.x = e0.x + p.x; r0.y = e0.y + p.y; r0.z = e0.z + p.z; r0.w = e0.w + p.w;
            r1.x = e1.x + p.x; r1.y = e1.y + p.y; r1.z = e1.z + p.z; r1.w = e1.w + p.w;
            __stcs(&out[ob0 + (size_t)u * 256], r0);
            __stcs(&out[ob1 + (size_t)u * 256], r1);
        }
        __syncthreads();
    }

    // passthrough lengths appended after the joint output
    if (writeTail && blockIdx.x == 0 && blockIdx.y == 0 && tid < 16) {
        float* o = (float*)out;
        size_t tb = (size_t)MOUT * Vc;
        if (tid < 8) o[tb + tid] = (float)slen[tid];
        else         o[tb + tid] = (float)tlen[tid - 8];
    }
}

extern "C" void kernel_launch(void* const* d_in, const int* in_sizes, int n_in,
                              void* d_out, int out_size)
{
    const float* enc  = (const float*)d_in[0];  // [B,T,D]
    const int*   slen = (const int*)  d_in[1];  // [B]
    const float* pred = (const float*)d_in[2];  // [B,U,D]
    const int*   tlen = (const int*)  d_in[3];  // [B]
    const float* W    = (const float*)d_in[4];  // [V, 2D]
    const float* bias = (const float*)d_in[5];  // [V]
    float* out = (float*)d_out;

    int smemBytes = (int)sizeof(Smem);
    cudaFuncSetAttribute(fused_joiner,
                         cudaFuncAttributeMaxDynamicSharedMemorySize, smemBytes);

    int writeTail = (out_size >= (int)((size_t)MOUT * Vc + 16)) ? 1 : 0;
    fused_joiner<<<dim3(Vc / 128, 2 * Bc), 512, smemBytes>>>(
        enc, pred, W, bias, (float4*)out, slen, tlen, writeTail);
}